// round 17
// baseline (speedup 1.0000x reference)
#include <cuda_runtime.h>
#include <cstdint>

#define NLEV 5
#define BATCH 128
#define NBOX 64

static __constant__ int c_Hc[NLEV] = {334, 167, 84, 42, 21};
static __constant__ int c_Wc[NLEV] = {200, 100, 50, 25, 13};

// float4 counts per level: (128*H*W)/4
// L0 2137600 | L1 534400 | L2 134400 | L3 33600 | L4 8736  (total 2848736)

#define CNT_BLOCKS   768
#define TOTAL_BLOCKS 1184            // one full wave at 8 blocks/SM
#define THREADS      256
#define NWARP        8
#define PS_W         296             // TOTAL_BLOCKS/4 float4 per level

__device__ float4       p_sum4[NLEV][PS_W];
__device__ uint4        p_cnt4[CNT_BLOCKS / 4];
__device__ unsigned int g_done;   // zero at load; reset by last block

// ---------------------------------------------------------------------------
// Two-stage span sum: (1) exact-count L2 prefetch of the whole span
// (fire-and-forget, frees the MSHR budget from DRAM latency), (2) loads.
// ---------------------------------------------------------------------------
__device__ __forceinline__ float4 ldg_nc(const float4* __restrict__ ap) {
    float4 v;
    asm("ld.global.nc.v4.f32 {%0,%1,%2,%3}, [%4];"
        : "=f"(v.x), "=f"(v.y), "=f"(v.z), "=f"(v.w) : "l"(ap));
    return v;
}

template <int U>
__device__ __forceinline__ float span_sum(const float4* __restrict__ p,
                                          int base, int lane) {
    const char* cp = reinterpret_cast<const char*>(p + base);
    constexpr int LINES = U * 4;              // 128B lines in span
#pragma unroll
    for (int j = 0; j < (LINES + 31) / 32; j++) {
        int li = j * 32 + lane;
        if (li < LINES)
            asm volatile("prefetch.global.L2 [%0];" :: "l"(cp + li * 128));
    }
    float a0 = 0.f, a1 = 0.f, a2 = 0.f, a3 = 0.f;
#pragma unroll
    for (int u = 0; u < U; u++) {
        float4 v = ldg_nc(p + base + u * 32 + lane);
        float t = (v.x + v.y) + (v.z + v.w);
        switch (u & 3) {
            case 0: a0 += t; break;
            case 1: a1 += t; break;
            case 2: a2 += t; break;
            default: a3 += t; break;
        }
    }
    return (a0 + a1) + (a2 + a3);
}

// ---------------------------------------------------------------------------
// Count setup (warps 6-7 of count blocks, 64 threads): x-masks + row marking.
// sb (u32): x-masks [64*STRIDE] | act_lo[HB] | act_hi[HB]
// ---------------------------------------------------------------------------
template <int H, int W, int HB>
__device__ __forceinline__ void count_setup(const float4* __restrict__ boxes4,
                                            int b, int row0, unsigned int* sb) {
    constexpr int   NW     = (W + 31) / 32;
    constexpr int   STRIDE = (NW | 1);
    constexpr float sx     = (float)(W / 800.0);
    constexpr float sy     = (float)(H / 1333.0);

    unsigned int* s_xm = sb;
    unsigned int* s_lo = sb + NBOX * STRIDE;
    unsigned int* s_hi = s_lo + HB;
    int ctid = threadIdx.x - 192;            // 0..63

    for (int i = ctid; i < 2 * HB; i += 64) s_lo[i] = 0u;
    asm volatile("bar.sync 1, 64;" ::: "memory");   // warps 6+7 only

    float4 bp = boxes4[b * NBOX + ctid];
    float fx1 = fminf(fmaxf(rintf(bp.x * sx), 0.0f), (float)(W - 1));
    float fy1 = fminf(fmaxf(rintf(bp.y * sy), 0.0f), (float)(H - 1));
    float fx2 = fminf(fmaxf(rintf(bp.z * sx), 0.0f), (float)W);
    float fy2 = fminf(fmaxf(rintf(bp.w * sy), 0.0f), (float)H);
    int ix1 = (int)fx1, iy1 = (int)fy1, ix2 = (int)fx2, iy2 = (int)fy2;
    bool valid = (fx2 > fx1) && (fy2 > fy1);

#pragma unroll
    for (int wi = 0; wi < NW; wi++) {
        int lo = ix1 - wi * 32;
        int hi = ix2 - wi * 32;
        lo = lo < 0 ? 0 : lo;
        hi = hi > 32 ? 32 : hi;
        unsigned int wmask = 0u;
        if (hi > lo) {
            unsigned int hm = (hi == 32) ? 0xFFFFFFFFu : ((1u << hi) - 1u);
            wmask = hm & (0xFFFFFFFFu << lo);
        }
        s_xm[ctid * STRIDE + wi] = wmask;
    }

    int ya = iy1 < row0 ? row0 : iy1;
    int yb = iy2 > row0 + HB ? row0 + HB : iy2;
    if (valid) {
        unsigned int  bit = 1u << (ctid & 31);
        unsigned int* tgt = (ctid < 32) ? s_lo : s_hi;
        for (int r = ya; r < yb; r++) atomicOr(&tgt[r - row0], bit);
    }
}

template <int H, int W, int HB>
__device__ __forceinline__ unsigned int count_rows(unsigned int* sb) {
    constexpr int NW     = (W + 31) / 32;
    constexpr int STRIDE = (NW | 1);

    unsigned int* s_xm = sb;
    unsigned int* s_lo = sb + NBOX * STRIDE;
    unsigned int* s_hi = s_lo + HB;
    int ctid = threadIdx.x - 192;

    unsigned int cnt = 0;
    for (int rr = ctid; rr < HB; rr += 64) {
        unsigned int w[NW];
#pragma unroll
        for (int wi = 0; wi < NW; wi++) w[wi] = 0u;
        unsigned int mlo = s_lo[rr];
        unsigned int mhi = s_hi[rr];
        while (mlo) {
            int m = __ffs(mlo) - 1;
            mlo &= mlo - 1;
            const unsigned int* bm = &s_xm[m * STRIDE];
#pragma unroll
            for (int wi = 0; wi < NW; wi++) w[wi] |= bm[wi];
        }
        while (mhi) {
            int m = __ffs(mhi) - 1 + 32;
            mhi &= mhi - 1;
            const unsigned int* bm = &s_xm[m * STRIDE];
#pragma unroll
            for (int wi = 0; wi < NW; wi++) w[wi] |= bm[wi];
        }
#pragma unroll
        for (int wi = 0; wi < NW; wi++) cnt += (unsigned)__popc(w[wi]);
    }
    return cnt;
}

// ---------------------------------------------------------------------------
__global__ void __launch_bounds__(THREADS, 8)
work_kernel(const float* __restrict__ h0, const float* __restrict__ h1,
            const float* __restrict__ h2, const float* __restrict__ h3,
            const float* __restrict__ h4, const float* __restrict__ boxes,
            float* __restrict__ out) {
    __shared__ float        s_wsum[NWARP];
    __shared__ int          s_wlev[NWARP];
    __shared__ unsigned int s_cw[2];
    __shared__ unsigned int sb[800];

    int bx   = blockIdx.x;
    int tid  = threadIdx.x;
    int lane = tid & 31;
    int wid  = tid >> 5;

    bool is_cnt_blk  = (bx < CNT_BLOCKS);
    bool is_cnt_warp = is_cnt_blk && (wid >= 6);

    int clev = 0, cb = 0, crow0 = 0;
    if (is_cnt_blk) {
        if (bx < 256) { clev = 0; cb = bx >> 1; crow0 = (bx & 1) * 167; }
        else {
            int t = bx - 256;
            clev  = 1 + (t >> 7);
            cb    = t & 127;
        }
    }

    // ========== phase A: sum warps prefetch+load | count warps setup =======
    if (!is_cnt_warp) {
        float s = 0.0f;
        int lev = -1;
        if (is_cnt_blk) {
            int g = bx * 6 + wid;            // 0..4607, all on level 0
            lev = 0;
            s = span_sum<8>(reinterpret_cast<const float4*>(h0), g * 256, lane);
        } else {
            int q = (bx - CNT_BLOCKS) * NWARP + wid;   // 0..3327
            if (q < 1871) {
                lev = 0;
                s = span_sum<16>(reinterpret_cast<const float4*>(h0),
                                 1179648 + q * 512, lane);
            } else if (q < 2915) {
                int r = q - 1871;
                lev = 1;
                if (r < 1043)
                    s = span_sum<16>(reinterpret_cast<const float4*>(h1),
                                     r * 512, lane);
                else
                    s = span_sum<12>(reinterpret_cast<const float4*>(h1),
                                     534016, lane);
            } else if (q < 3178) {
                int r = q - 2915;
                lev = 2;
                if (r < 262)
                    s = span_sum<16>(reinterpret_cast<const float4*>(h2),
                                     r * 512, lane);
                else
                    s = span_sum<8>(reinterpret_cast<const float4*>(h2),
                                    134144, lane);
            } else if (q < 3244) {
                int r = q - 3178;
                lev = 3;
                if (r < 65)
                    s = span_sum<16>(reinterpret_cast<const float4*>(h3),
                                     r * 512, lane);
                else
                    s = span_sum<10>(reinterpret_cast<const float4*>(h3),
                                     33280, lane);
            } else if (q < 3262) {
                int r = q - 3244;
                lev = 4;
                if (r < 17)
                    s = span_sum<16>(reinterpret_cast<const float4*>(h4),
                                     r * 512, lane);
                else
                    s = span_sum<1>(reinterpret_cast<const float4*>(h4),
                                    8704, lane);
            }
        }
        if (lev >= 0) {
#pragma unroll
            for (int o = 16; o > 0; o >>= 1)
                s += __shfl_down_sync(0xffffffffu, s, o);
        }
        if (lane == 0) { s_wsum[wid] = s; s_wlev[wid] = lev; }
    } else {
        switch (clev) {
            case 0:  count_setup<334, 200, 167>(
                         reinterpret_cast<const float4*>(boxes), cb, crow0, sb);
                     break;
            case 1:  count_setup<167, 100, 167>(
                         reinterpret_cast<const float4*>(boxes), cb, 0, sb);
                     break;
            case 2:  count_setup<84, 50, 84>(
                         reinterpret_cast<const float4*>(boxes), cb, 0, sb);
                     break;
            case 3:  count_setup<42, 25, 42>(
                         reinterpret_cast<const float4*>(boxes), cb, 0, sb);
                     break;
            default: count_setup<21, 13, 21>(
                         reinterpret_cast<const float4*>(boxes), cb, 0, sb);
                     break;
        }
    }
    __syncthreads();

    // ========== phase B: thread 0 combines sums | count warps do rows ======
    if (tid == 0) {
        int ns = is_cnt_blk ? 6 : NWARP;
        float acc0 = 0.f, acc1 = 0.f, acc2 = 0.f, acc3 = 0.f, acc4 = 0.f;
        for (int w2 = 0; w2 < ns; w2++) {
            int   l = s_wlev[w2];
            float v = s_wsum[w2];
            acc0 += (l == 0) ? v : 0.f;
            acc1 += (l == 1) ? v : 0.f;
            acc2 += (l == 2) ? v : 0.f;
            acc3 += (l == 3) ? v : 0.f;
            acc4 += (l == 4) ? v : 0.f;
        }
        float* ps = reinterpret_cast<float*>(&p_sum4[0][0]);
        ps[0 * TOTAL_BLOCKS + bx] = acc0;
        ps[1 * TOTAL_BLOCKS + bx] = acc1;
        ps[2 * TOTAL_BLOCKS + bx] = acc2;
        ps[3 * TOTAL_BLOCKS + bx] = acc3;
        ps[4 * TOTAL_BLOCKS + bx] = acc4;
    }
    if (is_cnt_warp) {
        unsigned int cnt;
        switch (clev) {
            case 0:  cnt = count_rows<334, 200, 167>(sb); break;
            case 1:  cnt = count_rows<167, 100, 167>(sb); break;
            case 2:  cnt = count_rows<84, 50, 84>(sb);    break;
            case 3:  cnt = count_rows<42, 25, 42>(sb);    break;
            default: cnt = count_rows<21, 13, 21>(sb);    break;
        }
#pragma unroll
        for (int o = 16; o > 0; o >>= 1)
            cnt += __shfl_down_sync(0xffffffffu, cnt, o);
        if (lane == 0) s_cw[wid - 6] = cnt;
    }
    __syncthreads();

    if (is_cnt_blk && tid == 0)
        reinterpret_cast<unsigned int*>(&p_cnt4[0])[bx] = s_cw[0] + s_cw[1];

    // ========== completion ticket -> finalize ==============================
    __shared__ bool is_last;
    __threadfence();
    if (tid == 0) {
        unsigned int v = atomicAdd(&g_done, 1u);
        is_last = (v == TOTAL_BLOCKS - 1);
    }
    __syncthreads();
    if (!is_last) return;
    __threadfence();

    __shared__ double s_d2[NLEV];
    if (wid < NLEV) {
        int lev = wid;
        double s = 0.0;
        for (int i = lane; i < PS_W; i += 32) {
            float4 v = p_sum4[lev][i];
            s += (double)((v.x + v.y) + (v.z + v.w));
        }
        unsigned int c = 0;
        if (lev == 0) {
            for (int i = lane; i < 64; i += 32) {
                uint4 v = p_cnt4[i];
                c += v.x + v.y + v.z + v.w;
            }
        } else {
            int base = 64 + (lev - 1) * 32;
            uint4 v = p_cnt4[base + lane];
            c += v.x + v.y + v.z + v.w;
        }
#pragma unroll
        for (int o = 16; o > 0; o >>= 1) {
            s += __shfl_down_sync(0xffffffffu, s, o);
            c += __shfl_down_sync(0xffffffffu, c, o);
        }
        if (lane == 0) {
            double tn = (double)BATCH * (double)c_Hc[lev] * (double)c_Wc[lev];
            double d  = s / tn - (double)c / tn;
            s_d2[lev] = d * d;
        }
    }
    __syncthreads();
    if (tid == 0) {
        double acc = s_d2[0] + s_d2[1] + s_d2[2] + s_d2[3] + s_d2[4];
        out[0] = (float)(acc / (double)NLEV);
        atomicExch(&g_done, 0u);
    }
}

// ---------------------------------------------------------------------------
extern "C" void kernel_launch(void* const* d_in, const int* in_sizes, int n_in,
                              void* d_out, int out_size) {
    (void)in_sizes; (void)n_in; (void)out_size;
    const float* h0    = (const float*)d_in[0];
    const float* h1    = (const float*)d_in[1];
    const float* h2    = (const float*)d_in[2];
    const float* h3    = (const float*)d_in[3];
    const float* h4    = (const float*)d_in[4];
    const float* boxes = (const float*)d_in[5];
    float* out = (float*)d_out;

    work_kernel<<<TOTAL_BLOCKS, THREADS>>>(h0, h1, h2, h3, h4, boxes, out);
}